// round 8
// baseline (speedup 1.0000x reference)
#include <cuda_runtime.h>
#include <cstdint>

#define RADIUS 5
#define KS 11
#define IMG_H 256
#define IMG_W 256
#define HW (IMG_H * IMG_W)
#define NTX 16           // thread x: owns cols 2tx, 2tx+1
#define NTY 2            // thread y: owns rows 2ty, 2ty+1
#define TZ 4             // window split: 3 of 12 rows per tz
#define OUTX 32
#define OUTY 4
#define TX 42            // halo width (32 + 10)
#define TYR 14           // halo height (4 + 10)
#define PLANE (TYR * TX) // 588
// per-pixel smem: G0(16) G1(16) P1(16) P2(16) P3(4) = 68 B
#define SMEM_BYTES (PLANE * 68)
#define OFF_G1 (16 * PLANE)
#define OFF_P1 (32 * PLANE)
#define OFF_P2 (48 * PLANE)
#define OFF_P3 (64 * PLANE)

// ---------------------------------------------------------------------------
// packed f32x2 helpers (bilateral chain only)
// ---------------------------------------------------------------------------
__device__ __forceinline__ uint64_t pk2(float lo, float hi) {
    uint64_t r; asm("mov.b64 %0, {%1,%2};" : "=l"(r) : "f"(lo), "f"(hi)); return r;
}
__device__ __forceinline__ void unpk2(float& lo, float& hi, uint64_t v) {
    asm("mov.b64 {%0,%1}, %2;" : "=f"(lo), "=f"(hi) : "l"(v));
}
__device__ __forceinline__ uint64_t add2(uint64_t a, uint64_t b) {
    uint64_t d; asm("add.rn.f32x2 %0,%1,%2;" : "=l"(d) : "l"(a), "l"(b)); return d;
}
__device__ __forceinline__ uint64_t mul2(uint64_t a, uint64_t b) {
    uint64_t d; asm("mul.rn.f32x2 %0,%1,%2;" : "=l"(d) : "l"(a), "l"(b)); return d;
}
__device__ __forceinline__ uint64_t fma2(uint64_t a, uint64_t b, uint64_t c) {
    uint64_t d; asm("fma.rn.f32x2 %0,%1,%2,%3;" : "=l"(d) : "l"(a), "l"(b), "l"(c)); return d;
}

// ---------------------------------------------------------------------------
// f32 ndtri replicating jax.scipy.special.ndtri (cephes, no FMA contraction).
// ---------------------------------------------------------------------------
template <int N>
__device__ __forceinline__ float polevl_f(float x, const float (&c)[N]) {
    float r = c[0];
#pragma unroll
    for (int i = 1; i < N; ++i) r = __fadd_rn(__fmul_rn(r, x), c[i]);
    return r;
}

__device__ float ndtri_f32(float p) {
    const float P0[5] = {-5.99633501014107895267e1f, 9.80010754185999661536e1f,
                         -5.66762857469070293439e1f, 1.39312609387279679503e1f,
                         -1.23916583867381258016e0f};
    const float Q0[9] = {1.0f, 1.95448858338141759834e0f, 4.67627912898881538453e0f,
                         8.63602421390890590575e1f, -2.25462687854119370527e2f,
                         2.00260212380060660359e2f, -8.20372256168538034246e1f,
                         1.59056225126211695515e1f, -1.18331621121330003142e0f};
    const float P1c[9] = {4.05544892305962419923e0f, 3.15251094599893866154e1f,
                          5.71628192246421288162e1f, 4.40805073893200834700e1f,
                          1.46849561928858024014e1f, 2.18663306850790267539e0f,
                          -1.40256079171354495875e-1f, -3.50424626827848203418e-2f,
                          -8.57456785154685413611e-4f};
    const float Q1c[9] = {1.0f, 1.57799883256466749731e1f, 4.53907635128879210584e1f,
                          4.13172038254672030440e1f, 1.50425385692907503408e1f,
                          2.50464946208309415979e0f, -1.42182922854787788574e-1f,
                          -3.80806407691578277194e-2f, -9.33259480895457427372e-4f};
    const float P2c[9] = {3.23774891776946035970e0f, 6.91522889068984211695e0f,
                          3.93881025292474443415e0f, 1.33303460815807542389e0f,
                          2.01485389549179081538e-1f, 1.23716634817820021358e-2f,
                          3.01581553508235416007e-4f, 2.65806974686737550832e-6f,
                          6.23974539184983651783e-9f};
    const float Q2c[9] = {1.0f, 6.02427039364742014255e0f, 3.67983563856160859403e0f,
                          1.37702099489081330271e0f, 2.16236993594496635890e-1f,
                          1.34204006088543189037e-2f, 3.28014464682127739104e-4f,
                          2.89247864745380683936e-6f, 6.79019408009981274425e-9f};
    const float one_m_expm2 = 0.86466471676338730811f;
    const float expm2 = 0.13533528323661269189f;

    float mcp = (p > one_m_expm2) ? __fadd_rn(1.0f, -p) : p;
    float san = (mcp <= 0.0f) ? 0.5f : mcp;
    float x;
    if (san > expm2) {
        float w = __fadd_rn(san, -0.5f);
        float ww = __fmul_rn(w, w);
        float r = __fdiv_rn(polevl_f(ww, P0), polevl_f(ww, Q0));
        x = __fadd_rn(w, __fmul_rn(__fmul_rn(w, ww), r));
        x = __fmul_rn(x, -2.50662827463100050242f);
    } else {
        float z = __fsqrt_rn(__fmul_rn(-2.0f, logf(san)));
        float ft = __fadd_rn(z, -__fdiv_rn(logf(z), z));
        float iz = __fdiv_rn(1.0f, z);
        float num, den;
        if (z >= 8.0f) { num = polevl_f(iz, P2c); den = polevl_f(iz, Q2c); }
        else           { num = polevl_f(iz, P1c); den = polevl_f(iz, Q1c); }
        float st = __fdiv_rn(__fdiv_rn(num, den), z);
        x = __fadd_rn(ft, -st);
    }
    return (p > one_m_expm2) ? x : -x;
}

__device__ float compute_gamma(int spp) {
    float z = ndtri_f32(0.9975f);
    double df = (double)(2 * spp - 2);
    float z2 = __fmul_rn(z, z);
    float z3 = __fmul_rn(z, z2);
    float z4 = __fmul_rn(z2, z2);
    float z5 = __fmul_rn(z, z4);
    float z7 = __fmul_rn(z3, z4);
    float g1 = __fdiv_rn(__fadd_rn(z3, z), (float)(4.0 * df));
    float g2 = __fdiv_rn(
        __fadd_rn(__fadd_rn(__fmul_rn(5.0f, z5), __fmul_rn(16.0f, z3)), __fmul_rn(3.0f, z)),
        (float)(96.0 * df * df));
    float g3 = __fdiv_rn(
        __fadd_rn(__fadd_rn(__fadd_rn(__fmul_rn(3.0f, z7), __fmul_rn(19.0f, z5)),
                            __fmul_rn(17.0f, z3)),
                  -__fmul_rn(15.0f, z)),
        (float)(384.0 * df * df * df));
    return __fadd_rn(__fadd_rn(__fadd_rn(z, g1), g2), g3);
}

// ---------------------------------------------------------------------------
// Denoiser: block (16,2,4)=128 thr, 512 blocks, 32x4 output tile.
// Each (tx,ty) thread owns a 2x2 block of output pixels; every staged neighbor
// load serves all 4 centers (12x12 window union, tz splits rows 4-way).
// ---------------------------------------------------------------------------
__global__ void __launch_bounds__(128, 4)
denoise_kernel(const float* __restrict__ img, const float* __restrict__ gd,
               const float* __restrict__ est, const float* __restrict__ var,
               const int* __restrict__ spp_p, float* __restrict__ out) {
    extern __shared__ char smraw[];
    float4* G0 = (float4*)smraw;
    float4* G1 = (float4*)(smraw + OFF_G1);
    float4* P1 = (float4*)(smraw + OFF_P1);
    float4* P2 = (float4*)(smraw + OFF_P2);
    float*  P3 = (float*) (smraw + OFF_P3);
    __shared__ float s_g2;

    const int tx = threadIdx.x, ty = threadIdx.y, tz = threadIdx.z;
    const int tid = (tz * NTY + ty) * NTX + tx;
    const int gx0 = blockIdx.x * OUTX - RADIUS;
    const int gy0 = blockIdx.y * OUTY - RADIUS;
    const float NINF = __int_as_float(0xff800000);
    // sqrt(0.5 * sigma_c * log2(e))
    const float SCA = 0.26857906f;   // sigma 0.1
    const float SCB = 6.00561167f;   // sigma 50
    const float SCC = 2.68579063f;   // sigma 10

    for (int i = tid; i < PLANE; i += 128) {
        int ly = i / TX, lx = i - ly * TX;
        int gy = gy0 + ly, gx = gx0 + lx;
        bool inb = ((unsigned)gy < IMG_H) & ((unsigned)gx < IMG_W);
        int g = gy * IMG_W + gx;
        float4 a, b, p1, p2; float p3;
        if (inb) {
            a = make_float4(gd[g] * SCA, gd[HW + g] * SCA,
                            gd[2 * HW + g] * SCB, gd[3 * HW + g] * SCB);
            b = make_float4(gd[4 * HW + g] * SCB, gd[5 * HW + g] * SCC,
                            gd[6 * HW + g] * SCC, gd[7 * HW + g] * SCC);
            float v0 = var[g], v1 = var[HW + g], v2 = var[2 * HW + g];
            v0 = (v0 == 0.f) ? NINF : v0;
            v1 = (v1 == 0.f) ? NINF : v1;
            v2 = (v2 == 0.f) ? NINF : v2;
            p1 = make_float4(est[g], v0, est[HW + g], v1);
            p2 = make_float4(est[2 * HW + g], v2, img[g], img[HW + g]);
            p3 = img[2 * HW + g];
        } else {
            a = make_float4(0.f, 0.f, 0.f, 0.f); b = a;
            p1 = make_float4(0.f, NINF, 0.f, NINF);
            p2 = make_float4(0.f, NINF, 0.f, 0.f);
            p3 = 0.f;
        }
        G0[i] = a; G1[i] = b; P1[i] = p1; P2[i] = p2; P3[i] = p3;
    }
    if (tid == 0) { float gm = compute_gamma(spp_p[0]); s_g2 = gm * gm; }
    __syncthreads();
    const float g2 = s_g2;
    const unsigned sbase = (unsigned)__cvta_generic_to_shared(smraw);

    // 4 center pixels: (2tx+i, 2ty+j), i,j in {0,1}. Halo-local indices:
    const int cbase = (2 * ty + RADIUS) * TX + 2 * tx + RADIUS;
    // k = j*2+i: 0=TL 1=TR 2=BL 3=BR
    uint64_t na[4], nb[4], nc[4], nd[4];
    float ce0[4], cv0[4], ce1[4], cv1[4], ce2[4], cv2[4];
#pragma unroll
    for (int k = 0; k < 4; ++k) {
        int ci = cbase + (k >> 1) * TX + (k & 1);
        float4 cg = G0[ci], ch = G1[ci];
        na[k] = pk2(-cg.x, -cg.y); nb[k] = pk2(-cg.z, -cg.w);
        nc[k] = pk2(-ch.x, -ch.y); nd[k] = pk2(-ch.z, -ch.w);
        float4 q1 = P1[ci], q2 = P2[ci];
        ce0[k] = q1.x; cv0[k] = q1.y; ce1[k] = q1.z; cv1[k] = q1.w;
        ce2[k] = q2.x; cv2[k] = q2.y;
    }

    float sw[4] = {0.f, 0.f, 0.f, 0.f};
    float a0[4] = {0.f, 0.f, 0.f, 0.f};
    float a1[4] = {0.f, 0.f, 0.f, 0.f};
    float a2[4] = {0.f, 0.f, 0.f, 0.f};
    const int rstart = tz * 3;

#pragma unroll 1
    for (int rr = 0; rr < 3; ++rr) {
        const int r = rstart + rr;                   // 0..11 over 12-row span
        const bool rt = (r <= 10), rb = (r >= 1);    // top/bottom row active
        const bool ft = (r == RADIUS), fb = (r == RADIUS + 1);
        const int rowb = (2 * ty + r) * TX + 2 * tx;
        const unsigned ga = sbase + (unsigned)(rowb * 16);
#pragma unroll
        for (int c = 0; c < 12; ++c) {
            const int ni = rowb + c;
            const bool cl = (c <= 10), cr = (c >= 1);   // left/right col active
            const bool gl = (c == RADIUS), gr = (c == RADIUS + 1);
            uint64_t g01, g23, g45, g67;
            asm("ld.shared.v2.u64 {%0,%1}, [%2];"
                : "=l"(g01), "=l"(g23) : "r"(ga + c * 16));
            asm("ld.shared.v2.u64 {%0,%1}, [%2];"
                : "=l"(g45), "=l"(g67) : "r"(ga + c * 16 + OFF_G1));
            const float4 p1 = P1[ni];               // e0,v0,e1,v1
            const float4 p2 = P2[ni];               // e2,v2,i0,i1
            const float i2 = P3[ni];

            const bool act[4] = {rt & cl, rt & cr, rb & cl, rb & cr};
            const bool frc[4] = {ft & gl, ft & gr, fb & gl, fb & gr};
#pragma unroll
            for (int k = 0; k < 4; ++k) {
                // bilateral weight (u64 f32x2 chain)
                uint64_t da = add2(g01, na[k]), db = add2(g23, nb[k]);
                uint64_t dc = add2(g45, nc[k]), dd = add2(g67, nd[k]);
                uint64_t sA = mul2(da, da), sB = mul2(db, db);
                sA = fma2(dc, dc, sA); sB = fma2(dd, dd, sB);
                sA = add2(sA, sB);
                float lo, hi; unpk2(lo, hi, sA);
                float bw; asm("ex2.approx.f32 %0, %1;" : "=f"(bw) : "f"(-lo - hi));
                // membership (exact algebra; -inf poison excludes)
                float d, r0, r1, r2;
                d = ce0[k] - p1.x; r0 = fmaf(g2, cv0[k] + p1.y, -(d * d));
                d = ce1[k] - p1.z; r1 = fmaf(g2, cv1[k] + p1.w, -(d * d));
                d = ce2[k] - p2.x; r2 = fmaf(g2, cv2[k] + p2.y, -(d * d));
                bool mem = fminf(fminf(r0, r1), r2) > 0.f;
                float fw = ((mem & act[k]) | frc[k]) ? bw : 0.f;
                sw[k] += fw;
                a0[k] = fmaf(p2.z, fw, a0[k]);
                a1[k] = fmaf(p2.w, fw, a1[k]);
                a2[k] = fmaf(i2, fw, a2[k]);
            }
        }
    }

    // tz reduction through smem: R[tz*128 + localpix], localpix over 32x4 tile.
    __syncthreads();
    float4* R = (float4*)smraw;
#pragma unroll
    for (int k = 0; k < 4; ++k) {
        int lp = (2 * ty + (k >> 1)) * OUTX + 2 * tx + (k & 1);
        R[tz * 128 + lp] = make_float4(sw[k], a0[k], a1[k], a2[k]);
    }
    __syncthreads();
    {
        float4 u = R[tid], v = R[128 + tid], w = R[256 + tid], x = R[384 + tid];
        float swt = (u.x + v.x) + (w.x + x.x);
        float inv = __fdiv_rn(1.0f, fmaxf(swt, 1e-10f));
        int ox = blockIdx.x * OUTX + (tid & 31);
        int oy = blockIdx.y * OUTY + (tid >> 5);
        int o = oy * IMG_W + ox;
        out[o] = ((u.y + v.y) + (w.y + x.y)) * inv;
        out[HW + o] = ((u.z + v.z) + (w.z + x.z)) * inv;
        out[2 * HW + o] = ((u.w + v.w) + (w.w + x.w)) * inv;
    }
}

extern "C" void kernel_launch(void* const* d_in, const int* in_sizes, int n_in,
                              void* d_out, int out_size) {
    const float* img = (const float*)d_in[0];
    const float* gd  = (const float*)d_in[1];
    const float* est = (const float*)d_in[2];
    const float* var = (const float*)d_in[3];
    const int*   spp = (const int*)d_in[4];
    float* out = (float*)d_out;

    dim3 block(NTX, NTY, TZ);
    dim3 grid(IMG_W / OUTX, IMG_H / OUTY);
    denoise_kernel<<<grid, block, SMEM_BYTES>>>(img, gd, est, var, spp, out);
}

// round 9
// speedup vs baseline: 1.0434x; 1.0434x over previous
#include <cuda_runtime.h>
#include <cstdint>

#define RADIUS 5
#define KS 11
#define IMG_H 256
#define IMG_W 256
#define HW (IMG_H * IMG_W)
#define BX 32
#define BYT 2            // ty; each thread owns output rows 2ty, 2ty+1
#define TZ 4             // window split: 3 of 12 rows per tz
#define OUTY 4           // output rows per block
#define TX 42            // halo width (32 + 10)
#define TYR 14           // halo height (4 + 10)
#define PLANE (TYR * TX) // 588
// per-pixel smem: G0(16) G1(16) P1(16) P2(16) P3(4) = 68 B
#define SMEM_BYTES (PLANE * 68)
#define OFF_G1 (16 * PLANE)
#define OFF_P1 (32 * PLANE)
#define OFF_P2 (48 * PLANE)
#define OFF_P3 (64 * PLANE)

__device__ __forceinline__ float ex2f(float x) {
    float r; asm("ex2.approx.f32 %0, %1;" : "=f"(r) : "f"(x)); return r;
}

// ---------------------------------------------------------------------------
// f32 ndtri replicating jax.scipy.special.ndtri (cephes, no FMA contraction).
// ---------------------------------------------------------------------------
template <int N>
__device__ __forceinline__ float polevl_f(float x, const float (&c)[N]) {
    float r = c[0];
#pragma unroll
    for (int i = 1; i < N; ++i) r = __fadd_rn(__fmul_rn(r, x), c[i]);
    return r;
}

__device__ float ndtri_f32(float p) {
    const float P0[5] = {-5.99633501014107895267e1f, 9.80010754185999661536e1f,
                         -5.66762857469070293439e1f, 1.39312609387279679503e1f,
                         -1.23916583867381258016e0f};
    const float Q0[9] = {1.0f, 1.95448858338141759834e0f, 4.67627912898881538453e0f,
                         8.63602421390890590575e1f, -2.25462687854119370527e2f,
                         2.00260212380060660359e2f, -8.20372256168538034246e1f,
                         1.59056225126211695515e1f, -1.18331621121330003142e0f};
    const float P1c[9] = {4.05544892305962419923e0f, 3.15251094599893866154e1f,
                          5.71628192246421288162e1f, 4.40805073893200834700e1f,
                          1.46849561928858024014e1f, 2.18663306850790267539e0f,
                          -1.40256079171354495875e-1f, -3.50424626827848203418e-2f,
                          -8.57456785154685413611e-4f};
    const float Q1c[9] = {1.0f, 1.57799883256466749731e1f, 4.53907635128879210584e1f,
                          4.13172038254672030440e1f, 1.50425385692907503408e1f,
                          2.50464946208309415979e0f, -1.42182922854787788574e-1f,
                          -3.80806407691578277194e-2f, -9.33259480895457427372e-4f};
    const float P2c[9] = {3.23774891776946035970e0f, 6.91522889068984211695e0f,
                          3.93881025292474443415e0f, 1.33303460815807542389e0f,
                          2.01485389549179081538e-1f, 1.23716634817820021358e-2f,
                          3.01581553508235416007e-4f, 2.65806974686737550832e-6f,
                          6.23974539184983651783e-9f};
    const float Q2c[9] = {1.0f, 6.02427039364742014255e0f, 3.67983563856160859403e0f,
                          1.37702099489081330271e0f, 2.16236993594496635890e-1f,
                          1.34204006088543189037e-2f, 3.28014464682127739104e-4f,
                          2.89247864745380683936e-6f, 6.79019408009981274425e-9f};
    const float one_m_expm2 = 0.86466471676338730811f;
    const float expm2 = 0.13533528323661269189f;

    float mcp = (p > one_m_expm2) ? __fadd_rn(1.0f, -p) : p;
    float san = (mcp <= 0.0f) ? 0.5f : mcp;
    float x;
    if (san > expm2) {
        float w = __fadd_rn(san, -0.5f);
        float ww = __fmul_rn(w, w);
        float r = __fdiv_rn(polevl_f(ww, P0), polevl_f(ww, Q0));
        x = __fadd_rn(w, __fmul_rn(__fmul_rn(w, ww), r));
        x = __fmul_rn(x, -2.50662827463100050242f);
    } else {
        float z = __fsqrt_rn(__fmul_rn(-2.0f, logf(san)));
        float ft = __fadd_rn(z, -__fdiv_rn(logf(z), z));
        float iz = __fdiv_rn(1.0f, z);
        float num, den;
        if (z >= 8.0f) { num = polevl_f(iz, P2c); den = polevl_f(iz, Q2c); }
        else           { num = polevl_f(iz, P1c); den = polevl_f(iz, Q1c); }
        float st = __fdiv_rn(__fdiv_rn(num, den), z);
        x = __fadd_rn(ft, -st);
    }
    return (p > one_m_expm2) ? x : -x;
}

__device__ float compute_gamma(int spp) {
    float z = ndtri_f32(0.9975f);
    double df = (double)(2 * spp - 2);
    float z2 = __fmul_rn(z, z);
    float z3 = __fmul_rn(z, z2);
    float z4 = __fmul_rn(z2, z2);
    float z5 = __fmul_rn(z, z4);
    float z7 = __fmul_rn(z3, z4);
    float g1 = __fdiv_rn(__fadd_rn(z3, z), (float)(4.0 * df));
    float g2 = __fdiv_rn(
        __fadd_rn(__fadd_rn(__fmul_rn(5.0f, z5), __fmul_rn(16.0f, z3)), __fmul_rn(3.0f, z)),
        (float)(96.0 * df * df));
    float g3 = __fdiv_rn(
        __fadd_rn(__fadd_rn(__fadd_rn(__fmul_rn(3.0f, z7), __fmul_rn(19.0f, z5)),
                            __fmul_rn(17.0f, z3)),
                  -__fmul_rn(15.0f, z)),
        (float)(384.0 * df * df * df));
    return __fadd_rn(__fadd_rn(__fadd_rn(z, g1), g2), g3);
}

// ---------------------------------------------------------------------------
// Denoiser: block (32,2,4)=256 thr, 512 blocks, 32x4 output tile.
// Each (tx,ty) owns output rows 2ty,2ty+1; tz splits the 12-row span 4-way.
// PLAIN C inner loop (no packed inline asm): ptxas schedules/CSEs freely.
// ---------------------------------------------------------------------------
__global__ void __launch_bounds__(256, 3)
denoise_kernel(const float* __restrict__ img, const float* __restrict__ gd,
               const float* __restrict__ est, const float* __restrict__ var,
               const int* __restrict__ spp_p, float* __restrict__ out) {
    extern __shared__ char smraw[];
    float4* G0 = (float4*)smraw;
    float4* G1 = (float4*)(smraw + OFF_G1);
    float4* P1 = (float4*)(smraw + OFF_P1);
    float4* P2 = (float4*)(smraw + OFF_P2);
    float*  P3 = (float*) (smraw + OFF_P3);
    __shared__ float s_g2;

    const int tx = threadIdx.x, ty = threadIdx.y, tz = threadIdx.z;
    const int tid = (tz * BYT + ty) * BX + tx;
    const int gx0 = blockIdx.x * BX - RADIUS;
    const int gy0 = blockIdx.y * OUTY - RADIUS;
    const float NINF = __int_as_float(0xff800000);
    // sqrt(0.5 * sigma_c * log2(e))
    const float SCA = 0.26857906f;   // sigma 0.1
    const float SCB = 6.00561167f;   // sigma 50
    const float SCC = 2.68579063f;   // sigma 10

    for (int i = tid; i < PLANE; i += 256) {
        int ly = i / TX, lx = i - ly * TX;
        int gy = gy0 + ly, gx = gx0 + lx;
        bool inb = ((unsigned)gy < IMG_H) & ((unsigned)gx < IMG_W);
        int g = gy * IMG_W + gx;
        float4 a, b, p1, p2; float p3;
        if (inb) {
            a = make_float4(gd[g] * SCA, gd[HW + g] * SCA,
                            gd[2 * HW + g] * SCB, gd[3 * HW + g] * SCB);
            b = make_float4(gd[4 * HW + g] * SCB, gd[5 * HW + g] * SCC,
                            gd[6 * HW + g] * SCC, gd[7 * HW + g] * SCC);
            float v0 = var[g], v1 = var[HW + g], v2 = var[2 * HW + g];
            v0 = (v0 == 0.f) ? NINF : v0;
            v1 = (v1 == 0.f) ? NINF : v1;
            v2 = (v2 == 0.f) ? NINF : v2;
            p1 = make_float4(est[g], v0, est[HW + g], v1);
            p2 = make_float4(est[2 * HW + g], v2, img[g], img[HW + g]);
            p3 = img[2 * HW + g];
        } else {
            a = make_float4(0.f, 0.f, 0.f, 0.f); b = a;
            p1 = make_float4(0.f, NINF, 0.f, NINF);
            p2 = make_float4(0.f, NINF, 0.f, 0.f);
            p3 = 0.f;
        }
        G0[i] = a; G1[i] = b; P1[i] = p1; P2[i] = p2; P3[i] = p3;
    }
    if (tid == 0) { float gm = compute_gamma(spp_p[0]); s_g2 = gm * gm; }
    __syncthreads();
    const float g2 = s_g2;

    // Center data for both owned pixels (rows 2ty, 2ty+1).
    const int ci0 = (2 * ty + RADIUS) * TX + tx + RADIUS;
    const int ci1 = ci0 + TX;
    const float4 cga = G0[ci0], cgb = G1[ci0];
    const float4 cha = G0[ci1], chb = G1[ci1];
    const float4 q10 = P1[ci0], q20 = P2[ci0];
    const float4 q11 = P1[ci1], q21 = P2[ci1];
    const float ce00 = q10.x, cv00 = q10.y, ce01 = q10.z, cv01 = q10.w;
    const float ce02 = q20.x, cv02 = q20.y;
    const float ce10 = q11.x, cv10 = q11.y, ce11 = q11.z, cv11 = q11.w;
    const float ce12 = q21.x, cv12 = q21.y;

    float sw0 = 0.f, a00 = 0.f, a01 = 0.f, a02 = 0.f;
    float sw1 = 0.f, a10 = 0.f, a11 = 0.f, a12 = 0.f;
    const int rstart = tz * 3;

#pragma unroll
    for (int rr = 0; rr < 3; ++rr) {
        const int r = rstart + rr;                  // 0..11 over the 12-row span
        const bool act0 = (r <= 10), act1 = (r >= 1);
        const bool f0 = (r == RADIUS), f1 = (r == RADIUS + 1);
        const int rowb = (2 * ty + r) * TX + tx;
#pragma unroll
        for (int dx = 0; dx < KS; ++dx) {
            const int ni = rowb + dx;
            const float4 ga = G0[ni];
            const float4 gb = G1[ni];
            const float4 p1 = P1[ni];               // e0,v0,e1,v1
            const float4 p2 = P2[ni];               // e2,v2,i0,i1
            const float i2 = P3[ni];

            // bilateral weight, center 0 (two independent FMA chains)
            float d0 = ga.x - cga.x, d1 = ga.y - cga.y;
            float d2 = ga.z - cga.z, d3 = ga.w - cga.w;
            float d4 = gb.x - cgb.x, d5 = gb.y - cgb.y;
            float d6 = gb.z - cgb.z, d7 = gb.w - cgb.w;
            float sA = d0 * d0;          float sB = d1 * d1;
            sA = fmaf(d2, d2, sA);       sB = fmaf(d3, d3, sB);
            sA = fmaf(d4, d4, sA);       sB = fmaf(d5, d5, sB);
            sA = fmaf(d6, d6, sA);       sB = fmaf(d7, d7, sB);
            float bw0 = ex2f(-sA - sB);
            // bilateral weight, center 1
            float e0 = ga.x - cha.x, e1 = ga.y - cha.y;
            float e2 = ga.z - cha.z, e3 = ga.w - cha.w;
            float e4 = gb.x - chb.x, e5 = gb.y - chb.y;
            float e6 = gb.z - chb.z, e7 = gb.w - chb.w;
            float tA = e0 * e0;          float tB = e1 * e1;
            tA = fmaf(e2, e2, tA);       tB = fmaf(e3, e3, tB);
            tA = fmaf(e4, e4, tA);       tB = fmaf(e5, e5, tB);
            tA = fmaf(e6, e6, tA);       tB = fmaf(e7, e7, tB);
            float bw1 = ex2f(-tA - tB);

            // membership (exact algebra; -inf poison excludes), center 0
            float d, r0, r1, r2;
            d = ce00 - p1.x; r0 = fmaf(g2, cv00 + p1.y, -(d * d));
            d = ce01 - p1.z; r1 = fmaf(g2, cv01 + p1.w, -(d * d));
            d = ce02 - p2.x; r2 = fmaf(g2, cv02 + p2.y, -(d * d));
            bool mem0 = fminf(fminf(r0, r1), r2) > 0.f;
            // center 1
            d = ce10 - p1.x; r0 = fmaf(g2, cv10 + p1.y, -(d * d));
            d = ce11 - p1.z; r1 = fmaf(g2, cv11 + p1.w, -(d * d));
            d = ce12 - p2.x; r2 = fmaf(g2, cv12 + p2.y, -(d * d));
            bool mem1 = fminf(fminf(r0, r1), r2) > 0.f;

            if (dx == RADIUS) {                      // force own center pixel in
                mem0 = mem0 | f0;
                mem1 = mem1 | f1;
            }
            mem0 = mem0 & act0;
            mem1 = mem1 & act1;
            float fw0 = mem0 ? bw0 : 0.f;
            float fw1 = mem1 ? bw1 : 0.f;
            sw0 += fw0;
            a00 = fmaf(p2.z, fw0, a00); a01 = fmaf(p2.w, fw0, a01); a02 = fmaf(i2, fw0, a02);
            sw1 += fw1;
            a10 = fmaf(p2.z, fw1, a10); a11 = fmaf(p2.w, fw1, a11); a12 = fmaf(i2, fw1, a12);
        }
    }

    // 4-way tz reduction through smem (conflict-free layout R[tz*128 + pix]).
    __syncthreads();
    float4* R = (float4*)smraw;
    const int pix0 = (2 * ty) * BX + tx;
    R[tz * 128 + pix0] = make_float4(sw0, a00, a01, a02);
    R[tz * 128 + pix0 + BX] = make_float4(sw1, a10, a11, a12);
    __syncthreads();
    if (tid < 128) {
        float4 u = R[tid], v = R[128 + tid], w = R[256 + tid], x = R[384 + tid];
        float swt = (u.x + v.x) + (w.x + x.x);
        float inv = __fdiv_rn(1.0f, fmaxf(swt, 1e-10f));
        int ox = blockIdx.x * BX + (tid & 31);
        int oy = blockIdx.y * OUTY + (tid >> 5);
        int o = oy * IMG_W + ox;
        out[o] = ((u.y + v.y) + (w.y + x.y)) * inv;
        out[HW + o] = ((u.z + v.z) + (w.z + x.z)) * inv;
        out[2 * HW + o] = ((u.w + v.w) + (w.w + x.w)) * inv;
    }
}

extern "C" void kernel_launch(void* const* d_in, const int* in_sizes, int n_in,
                              void* d_out, int out_size) {
    const float* img = (const float*)d_in[0];
    const float* gd  = (const float*)d_in[1];
    const float* est = (const float*)d_in[2];
    const float* var = (const float*)d_in[3];
    const int*   spp = (const int*)d_in[4];
    float* out = (float*)d_out;

    dim3 block(BX, BYT, TZ);
    dim3 grid(IMG_W / BX, IMG_H / OUTY);
    denoise_kernel<<<grid, block, SMEM_BYTES>>>(img, gd, est, var, spp, out);
}

// round 10
// speedup vs baseline: 1.1564x; 1.1083x over previous
#include <cuda_runtime.h>
#include <cstdint>

#define RADIUS 5
#define KS 11
#define IMG_H 256
#define IMG_W 256
#define HW (IMG_H * IMG_W)
#define BX 32
#define BYT 2            // ty; each thread owns output rows 2ty, 2ty+1
#define TZ 4             // window split: 3 of 12 rows per tz
#define OUTY 4           // output rows per block
#define TX 42            // halo width (32 + 10)
#define TYR 14           // halo height (4 + 10)
#define PLANE (TYR * TX) // 588
// per-pixel smem: G0(16) G1(16) E(16: se0,N0,se1,N1) F(16: se2,N2,i0,i1)
//                 H(8: i2,Q)  -> 72 B
#define SMEM_BYTES (PLANE * 72)
#define OFF_G1 (16 * PLANE)
#define OFF_E  (32 * PLANE)
#define OFF_F  (48 * PLANE)
#define OFF_H  (64 * PLANE)

__device__ __forceinline__ float ex2f(float x) {
    float r; asm("ex2.approx.f32 %0, %1;" : "=f"(r) : "f"(x)); return r;
}

// ---------------------------------------------------------------------------
// f32 ndtri replicating jax.scipy.special.ndtri (cephes, no FMA contraction).
// ---------------------------------------------------------------------------
template <int N>
__device__ __forceinline__ float polevl_f(float x, const float (&c)[N]) {
    float r = c[0];
#pragma unroll
    for (int i = 1; i < N; ++i) r = __fadd_rn(__fmul_rn(r, x), c[i]);
    return r;
}

__device__ float ndtri_f32(float p) {
    const float P0[5] = {-5.99633501014107895267e1f, 9.80010754185999661536e1f,
                         -5.66762857469070293439e1f, 1.39312609387279679503e1f,
                         -1.23916583867381258016e0f};
    const float Q0[9] = {1.0f, 1.95448858338141759834e0f, 4.67627912898881538453e0f,
                         8.63602421390890590575e1f, -2.25462687854119370527e2f,
                         2.00260212380060660359e2f, -8.20372256168538034246e1f,
                         1.59056225126211695515e1f, -1.18331621121330003142e0f};
    const float P1c[9] = {4.05544892305962419923e0f, 3.15251094599893866154e1f,
                          5.71628192246421288162e1f, 4.40805073893200834700e1f,
                          1.46849561928858024014e1f, 2.18663306850790267539e0f,
                          -1.40256079171354495875e-1f, -3.50424626827848203418e-2f,
                          -8.57456785154685413611e-4f};
    const float Q1c[9] = {1.0f, 1.57799883256466749731e1f, 4.53907635128879210584e1f,
                          4.13172038254672030440e1f, 1.50425385692907503408e1f,
                          2.50464946208309415979e0f, -1.42182922854787788574e-1f,
                          -3.80806407691578277194e-2f, -9.33259480895457427372e-4f};
    const float P2c[9] = {3.23774891776946035970e0f, 6.91522889068984211695e0f,
                          3.93881025292474443415e0f, 1.33303460815807542389e0f,
                          2.01485389549179081538e-1f, 1.23716634817820021358e-2f,
                          3.01581553508235416007e-4f, 2.65806974686737550832e-6f,
                          6.23974539184983651783e-9f};
    const float Q2c[9] = {1.0f, 6.02427039364742014255e0f, 3.67983563856160859403e0f,
                          1.37702099489081330271e0f, 2.16236993594496635890e-1f,
                          1.34204006088543189037e-2f, 3.28014464682127739104e-4f,
                          2.89247864745380683936e-6f, 6.79019408009981274425e-9f};
    const float one_m_expm2 = 0.86466471676338730811f;
    const float expm2 = 0.13533528323661269189f;

    float mcp = (p > one_m_expm2) ? __fadd_rn(1.0f, -p) : p;
    float san = (mcp <= 0.0f) ? 0.5f : mcp;
    float x;
    if (san > expm2) {
        float w = __fadd_rn(san, -0.5f);
        float ww = __fmul_rn(w, w);
        float r = __fdiv_rn(polevl_f(ww, P0), polevl_f(ww, Q0));
        x = __fadd_rn(w, __fmul_rn(__fmul_rn(w, ww), r));
        x = __fmul_rn(x, -2.50662827463100050242f);
    } else {
        float z = __fsqrt_rn(__fmul_rn(-2.0f, logf(san)));
        float ft = __fadd_rn(z, -__fdiv_rn(logf(z), z));
        float iz = __fdiv_rn(1.0f, z);
        float num, den;
        if (z >= 8.0f) { num = polevl_f(iz, P2c); den = polevl_f(iz, Q2c); }
        else           { num = polevl_f(iz, P1c); den = polevl_f(iz, Q1c); }
        float st = __fdiv_rn(__fdiv_rn(num, den), z);
        x = __fadd_rn(ft, -st);
    }
    return (p > one_m_expm2) ? x : -x;
}

__device__ float compute_gamma(int spp) {
    float z = ndtri_f32(0.9975f);
    double df = (double)(2 * spp - 2);
    float z2 = __fmul_rn(z, z);
    float z3 = __fmul_rn(z, z2);
    float z4 = __fmul_rn(z2, z2);
    float z5 = __fmul_rn(z, z4);
    float z7 = __fmul_rn(z3, z4);
    float g1 = __fdiv_rn(__fadd_rn(z3, z), (float)(4.0 * df));
    float g2 = __fdiv_rn(
        __fadd_rn(__fadd_rn(__fmul_rn(5.0f, z5), __fmul_rn(16.0f, z3)), __fmul_rn(3.0f, z)),
        (float)(96.0 * df * df));
    float g3 = __fdiv_rn(
        __fadd_rn(__fadd_rn(__fadd_rn(__fmul_rn(3.0f, z7), __fmul_rn(19.0f, z5)),
                            __fmul_rn(17.0f, z3)),
                  -__fmul_rn(15.0f, z)),
        (float)(384.0 * df * df * df));
    return __fadd_rn(__fadd_rn(__fadd_rn(z, g1), g2), g3);
}

// ---------------------------------------------------------------------------
// Denoiser with expanded quadratics:
//   bilateral: Sum (gn-gc)^2 = Qn + Qc - 2*dot(gn,gc), Q staged per pixel
//   membership: g2*(cv+sv) - d^2 = Nc + Nn + 2*ce*se, N = g2*v - e^2 staged
// block (32,2,4)=256 thr, 512 blocks, 32x4 output tile, tz splits rows 4-way.
// ---------------------------------------------------------------------------
__global__ void __launch_bounds__(256, 3)
denoise_kernel(const float* __restrict__ img, const float* __restrict__ gd,
               const float* __restrict__ est, const float* __restrict__ var,
               const int* __restrict__ spp_p, float* __restrict__ out) {
    extern __shared__ char smraw[];
    float4* G0 = (float4*)smraw;
    float4* G1 = (float4*)(smraw + OFF_G1);
    float4* E  = (float4*)(smraw + OFF_E);   // se0, N0, se1, N1
    float4* F  = (float4*)(smraw + OFF_F);   // se2, N2, i0, i1
    float2* H  = (float2*)(smraw + OFF_H);   // i2, Q

    const int tx = threadIdx.x, ty = threadIdx.y, tz = threadIdx.z;
    const int tid = (tz * BYT + ty) * BX + tx;
    const int gx0 = blockIdx.x * BX - RADIUS;
    const int gy0 = blockIdx.y * OUTY - RADIUS;
    const float NINF = __int_as_float(0xff800000);
    // sqrt(0.5 * sigma_c * log2(e))
    const float SCA = 0.26857906f;   // sigma 0.1
    const float SCB = 6.00561167f;   // sigma 50
    const float SCC = 2.68579063f;   // sigma 10

    // gamma^2: uniform, computed by every thread (no divergence, once).
    const float gm = compute_gamma(spp_p[0]);
    const float g2 = gm * gm;

    for (int i = tid; i < PLANE; i += 256) {
        int ly = i / TX, lx = i - ly * TX;
        int gy = gy0 + ly, gx = gx0 + lx;
        bool inb = ((unsigned)gy < IMG_H) & ((unsigned)gx < IMG_W);
        int g = gy * IMG_W + gx;
        float4 a, b, e4, f4; float2 h2;
        if (inb) {
            a = make_float4(gd[g] * SCA, gd[HW + g] * SCA,
                            gd[2 * HW + g] * SCB, gd[3 * HW + g] * SCB);
            b = make_float4(gd[4 * HW + g] * SCB, gd[5 * HW + g] * SCC,
                            gd[6 * HW + g] * SCC, gd[7 * HW + g] * SCC);
            float Q = a.x * a.x;
            Q = fmaf(a.y, a.y, Q); Q = fmaf(a.z, a.z, Q); Q = fmaf(a.w, a.w, Q);
            Q = fmaf(b.x, b.x, Q); Q = fmaf(b.y, b.y, Q);
            Q = fmaf(b.z, b.z, Q); Q = fmaf(b.w, b.w, Q);
            float e0 = est[g], e1 = est[HW + g], e2 = est[2 * HW + g];
            float v0 = var[g], v1 = var[HW + g], v2 = var[2 * HW + g];
            float N0 = (v0 == 0.f) ? NINF : fmaf(g2, v0, -(e0 * e0));
            float N1 = (v1 == 0.f) ? NINF : fmaf(g2, v1, -(e1 * e1));
            float N2 = (v2 == 0.f) ? NINF : fmaf(g2, v2, -(e2 * e2));
            e4 = make_float4(e0, N0, e1, N1);
            f4 = make_float4(e2, N2, img[g], img[HW + g]);
            h2 = make_float2(img[2 * HW + g], Q);
        } else {
            a = make_float4(0.f, 0.f, 0.f, 0.f); b = a;
            e4 = make_float4(0.f, NINF, 0.f, NINF);
            f4 = make_float4(0.f, NINF, 0.f, 0.f);
            h2 = make_float2(0.f, 0.f);
        }
        G0[i] = a; G1[i] = b; E[i] = e4; F[i] = f4; H[i] = h2;
    }
    __syncthreads();

    // Center constants for both owned pixels (rows 2ty, 2ty+1).
    const int ci0 = (2 * ty + RADIUS) * TX + tx + RADIUS;
    const int ci1 = ci0 + TX;
    const float4 cga = G0[ci0], cgb = G1[ci0];
    const float4 cha = G0[ci1], chb = G1[ci1];
    const float nQ0 = -H[ci0].y, nQ1 = -H[ci1].y;
    const float4 ce0 = E[ci0], cf0 = F[ci0];
    const float4 ce1 = E[ci1], cf1 = F[ci1];
    // per-channel: 2*ce and C (= staged N at center)
    const float w00 = 2.f * ce0.x, C00 = ce0.y;
    const float w01 = 2.f * ce0.z, C01 = ce0.w;
    const float w02 = 2.f * cf0.x, C02 = cf0.y;
    const float w10 = 2.f * ce1.x, C10 = ce1.y;
    const float w11 = 2.f * ce1.z, C11 = ce1.w;
    const float w12 = 2.f * cf1.x, C12 = cf1.y;

    float sw0 = 0.f, a00 = 0.f, a01 = 0.f, a02 = 0.f;
    float sw1 = 0.f, a10 = 0.f, a11 = 0.f, a12 = 0.f;
    const int rstart = tz * 3;

#pragma unroll
    for (int rr = 0; rr < 3; ++rr) {
        const int r = rstart + rr;                  // 0..11 over the 12-row span
        const bool act0 = (r <= 10), act1 = (r >= 1);
        const bool f0 = (r == RADIUS), f1 = (r == RADIUS + 1);
        const int rowb = (2 * ty + r) * TX + tx;
#pragma unroll
        for (int dx = 0; dx < KS; ++dx) {
            const int ni = rowb + dx;
            const float4 ga = G0[ni];
            const float4 gb = G1[ni];
            const float4 e = E[ni];                 // se0,N0,se1,N1
            const float4 f = F[ni];                 // se2,N2,i0,i1
            const float2 h = H[ni];                 // i2,Q

            // bilateral, center 0: arg = 2*dot - Qn - Qc
            float s0 = ga.x * cga.x;     float s1 = ga.y * cga.y;
            s0 = fmaf(ga.z, cga.z, s0);  s1 = fmaf(ga.w, cga.w, s1);
            s0 = fmaf(gb.x, cgb.x, s0);  s1 = fmaf(gb.y, cgb.y, s1);
            s0 = fmaf(gb.z, cgb.z, s0);  s1 = fmaf(gb.w, cgb.w, s1);
            float t0 = nQ0 - h.y;
            float bw0 = ex2f(fmaf(s0, 2.f, fmaf(s1, 2.f, t0)));
            // bilateral, center 1
            float u0 = ga.x * cha.x;     float u1 = ga.y * cha.y;
            u0 = fmaf(ga.z, cha.z, u0);  u1 = fmaf(ga.w, cha.w, u1);
            u0 = fmaf(gb.x, chb.x, u0);  u1 = fmaf(gb.y, chb.y, u1);
            u0 = fmaf(gb.z, chb.z, u0);  u1 = fmaf(gb.w, chb.w, u1);
            float t1 = nQ1 - h.y;
            float bw1 = ex2f(fmaf(u0, 2.f, fmaf(u1, 2.f, t1)));

            // membership, center 0: r = C + N + 2*ce*se  (>0 => in)
            float r0 = fmaf(w00, e.x, C00 + e.y);
            float r1 = fmaf(w01, e.z, C01 + e.w);
            float r2 = fmaf(w02, f.x, C02 + f.y);
            bool mem0 = fminf(fminf(r0, r1), r2) > 0.f;
            // center 1
            r0 = fmaf(w10, e.x, C10 + e.y);
            r1 = fmaf(w11, e.z, C11 + e.w);
            r2 = fmaf(w12, f.x, C12 + f.y);
            bool mem1 = fminf(fminf(r0, r1), r2) > 0.f;

            if (dx == RADIUS) {                      // force own center pixel in
                mem0 = mem0 | f0;
                mem1 = mem1 | f1;
            }
            mem0 = mem0 & act0;
            mem1 = mem1 & act1;
            float fw0 = mem0 ? bw0 : 0.f;
            float fw1 = mem1 ? bw1 : 0.f;
            sw0 += fw0;
            a00 = fmaf(f.z, fw0, a00); a01 = fmaf(f.w, fw0, a01); a02 = fmaf(h.x, fw0, a02);
            sw1 += fw1;
            a10 = fmaf(f.z, fw1, a10); a11 = fmaf(f.w, fw1, a11); a12 = fmaf(h.x, fw1, a12);
        }
    }

    // 4-way tz reduction through smem (conflict-free layout R[tz*128 + pix]).
    __syncthreads();
    float4* R = (float4*)smraw;
    const int pix0 = (2 * ty) * BX + tx;
    R[tz * 128 + pix0] = make_float4(sw0, a00, a01, a02);
    R[tz * 128 + pix0 + BX] = make_float4(sw1, a10, a11, a12);
    __syncthreads();
    if (tid < 128) {
        float4 u = R[tid], v = R[128 + tid], w = R[256 + tid], x = R[384 + tid];
        float swt = (u.x + v.x) + (w.x + x.x);
        float inv = __fdiv_rn(1.0f, fmaxf(swt, 1e-10f));
        int ox = blockIdx.x * BX + (tid & 31);
        int oy = blockIdx.y * OUTY + (tid >> 5);
        int o = oy * IMG_W + ox;
        out[o] = ((u.y + v.y) + (w.y + x.y)) * inv;
        out[HW + o] = ((u.z + v.z) + (w.z + x.z)) * inv;
        out[2 * HW + o] = ((u.w + v.w) + (w.w + x.w)) * inv;
    }
}

extern "C" void kernel_launch(void* const* d_in, const int* in_sizes, int n_in,
                              void* d_out, int out_size) {
    const float* img = (const float*)d_in[0];
    const float* gd  = (const float*)d_in[1];
    const float* est = (const float*)d_in[2];
    const float* var = (const float*)d_in[3];
    const int*   spp = (const int*)d_in[4];
    float* out = (float*)d_out;

    dim3 block(BX, BYT, TZ);
    dim3 grid(IMG_W / BX, IMG_H / OUTY);
    denoise_kernel<<<grid, block, SMEM_BYTES>>>(img, gd, est, var, spp, out);
}